// round 16
// baseline (speedup 1.0000x reference)
#include <cuda_runtime.h>
#include <cuda_bf16.h>
#include <cuda_fp16.h>
#include <cstdint>
#include <math.h>

#define B_ 2
#define S_ 2048
#define E_ 2048
#define H_ 32
#define D_ 64
#define M_ (B_*S_)
#define SCALE_ 0.125f

// ---------------- scratch ----------------
static __device__ __align__(128) int8_t g_x1[(size_t)M_ * E_];
static __device__ __align__(128) int8_t g_x2[(size_t)M_ * E_];
static __device__ __align__(128) float  g_sx[M_];
static __device__ __align__(128) int8_t g_a1[(size_t)M_ * E_];
static __device__ __align__(128) int8_t g_a2[(size_t)M_ * E_];
static __device__ __align__(128) float  g_sa2[(size_t)H_ * M_];

static __device__ __align__(128) int8_t g_wq1[(size_t)E_ * E_];
static __device__ __align__(128) int8_t g_wq2[(size_t)E_ * E_];
static __device__ __align__(128) float  g_swq[E_];
static __device__ __align__(128) int8_t g_wk1[(size_t)E_ * E_];
static __device__ __align__(128) int8_t g_wk2[(size_t)E_ * E_];
static __device__ __align__(128) float  g_swk[E_];
static __device__ __align__(128) int8_t g_wv1[(size_t)E_ * E_];
static __device__ __align__(128) int8_t g_wv2[(size_t)E_ * E_];
static __device__ __align__(128) float  g_swv[E_];
static __device__ __align__(128) int8_t g_wo1[(size_t)E_ * E_];
static __device__ __align__(128) int8_t g_wo2[(size_t)E_ * E_];
static __device__ __align__(128) float  g_swo[E_];

static __device__ __align__(128) int8_t g_q1[(size_t)M_ * E_];
static __device__ __align__(128) int8_t g_q2[(size_t)M_ * E_];
static __device__ __align__(128) int8_t g_k1[(size_t)M_ * E_];
static __device__ __align__(128) int8_t g_k2[(size_t)M_ * E_];
static __device__ __align__(128) float  g_sq[(size_t)H_ * M_];
static __device__ __align__(128) float  g_sk[(size_t)H_ * M_];

static __device__ __align__(128) __half g_vh[(size_t)M_ * E_];

// ---------------- helpers ----------------
__device__ __forceinline__ uint32_t smem_u32(const void* p) {
    uint32_t a;
    asm("{ .reg .u64 t; cvta.to.shared.u64 t, %1; cvt.u32.u64 %0, t; }"
        : "=r"(a) : "l"(p));
    return a;
}
__device__ __forceinline__ void cp_async16(uint32_t saddr, const void* gaddr) {
    asm volatile("cp.async.cg.shared.global [%0], [%1], 16;\n"
                 :: "r"(saddr), "l"(gaddr));
}
#define CP_COMMIT() asm volatile("cp.async.commit_group;\n" ::: "memory")
#define CP_WAIT0()  asm volatile("cp.async.wait_group 0;\n" ::: "memory")
#define CP_WAIT1()  asm volatile("cp.async.wait_group 1;\n" ::: "memory")
#define CP_WAIT2()  asm volatile("cp.async.wait_group 2;\n" ::: "memory")

__device__ __forceinline__ void ldm_x4(uint32_t* r, uint32_t addr) {
    asm volatile("ldmatrix.sync.aligned.m8n8.x4.shared.b16 {%0,%1,%2,%3}, [%4];"
                 : "=r"(r[0]), "=r"(r[1]), "=r"(r[2]), "=r"(r[3]) : "r"(addr));
}
__device__ __forceinline__ void ldm_x4t(uint32_t* r, uint32_t addr) {
    asm volatile("ldmatrix.sync.aligned.m8n8.x4.trans.shared.b16 {%0,%1,%2,%3}, [%4];"
                 : "=r"(r[0]), "=r"(r[1]), "=r"(r[2]), "=r"(r[3]) : "r"(addr));
}
__device__ __forceinline__ void mma_h(float* d, const uint32_t* a,
                                      uint32_t b0, uint32_t b1) {
    asm volatile(
        "mma.sync.aligned.m16n8k16.row.col.f32.f16.f16.f32 "
        "{%0,%1,%2,%3}, {%4,%5,%6,%7}, {%8,%9}, {%0,%1,%2,%3};"
        : "+f"(d[0]), "+f"(d[1]), "+f"(d[2]), "+f"(d[3])
        : "r"(a[0]), "r"(a[1]), "r"(a[2]), "r"(a[3]), "r"(b0), "r"(b1));
}
__device__ __forceinline__ void mma_s8(int* d, const uint32_t* a,
                                       uint32_t b0, uint32_t b1) {
    asm volatile(
        "mma.sync.aligned.m16n8k32.row.col.s32.s8.s8.s32 "
        "{%0,%1,%2,%3}, {%4,%5,%6,%7}, {%8,%9}, {%0,%1,%2,%3};"
        : "+r"(d[0]), "+r"(d[1]), "+r"(d[2]), "+r"(d[3])
        : "r"(a[0]), "r"(a[1]), "r"(a[2]), "r"(a[3]), "r"(b0), "r"(b1));
}
__device__ __forceinline__ uint32_t packh(float lo, float hi) {
    uint32_t d;
    asm("cvt.rn.f16x2.f32 %0, %1, %2;" : "=r"(d) : "f"(hi), "f"(lo));
    return d;
}
__device__ __forceinline__ uint32_t ex2h2(uint32_t x) {
    uint32_t y;
    asm("ex2.approx.f16x2 %0, %1;" : "=r"(y) : "r"(x));
    return y;
}
__device__ __forceinline__ float ex2(float x) {
    float y; asm("ex2.approx.f32 %0, %1;" : "=f"(y) : "f"(x)); return y;
}

// ---------------------------------------------------------------------------
// Row-wise two-level int8 quantization over 2048-col rows.
// ---------------------------------------------------------------------------
struct RQArgs { const float* src; int8_t* q1; int8_t* q2; float* s; int rows; };

__device__ __forceinline__ void rowquant_body(
    const float* __restrict__ x, int8_t* __restrict__ q1,
    int8_t* __restrict__ q2, float* __restrict__ s, int row, int t,
    float* wmax)
{
    const float* xr = x + (size_t)row * 2048 + t * 8;
    float4 v0 = ((const float4*)xr)[0];
    float4 v1 = ((const float4*)xr)[1];
    float vv[8] = {v0.x, v0.y, v0.z, v0.w, v1.x, v1.y, v1.z, v1.w};
    float m = 0.f;
#pragma unroll
    for (int j = 0; j < 8; j++) m = fmaxf(m, fabsf(vv[j]));
#pragma unroll
    for (int o = 16; o; o >>= 1) m = fmaxf(m, __shfl_xor_sync(~0u, m, o));
    if ((t & 31) == 0) wmax[t >> 5] = m;
    __syncthreads();
    float mm = wmax[0];
#pragma unroll
    for (int i = 1; i < 8; i++) mm = fmaxf(mm, wmax[i]);
    mm = fmaxf(mm, 1e-20f);
    if (t == 0) s[row] = mm * (1.f / 127.f);
    const float inv = 127.f / mm;

    uint32_t p1[2] = {0, 0}, p2[2] = {0, 0};
#pragma unroll
    for (int j = 0; j < 8; j++) {
        float xs = vv[j] * inv;
        float qf = rintf(xs);
        float rf = rintf((xs - qf) * 254.f);
        int iq = (int)qf, ir = (int)rf;
        p1[j >> 2] |= (uint32_t)(iq & 0xff) << ((j & 3) * 8);
        p2[j >> 2] |= (uint32_t)(ir & 0xff) << ((j & 3) * 8);
    }
    ((uint32_t*)q1)[row * 512 + t * 2]     = p1[0];
    ((uint32_t*)q1)[row * 512 + t * 2 + 1] = p1[1];
    ((uint32_t*)q2)[row * 512 + t * 2]     = p2[0];
    ((uint32_t*)q2)[row * 512 + t * 2 + 1] = p2[1];
}

__global__ __launch_bounds__(256) void rowquant5(
    RQArgs a0, RQArgs a1, RQArgs a2, RQArgs a3, RQArgs a4)
{
    __shared__ float wmax[8];
    RQArgs a = (blockIdx.y == 0) ? a0 : (blockIdx.y == 1) ? a1
             : (blockIdx.y == 2) ? a2 : (blockIdx.y == 3) ? a3 : a4;
    if ((int)blockIdx.x >= a.rows) return;
    rowquant_body(a.src, a.q1, a.q2, a.s, blockIdx.x, threadIdx.x, wmax);
}

// ---------------------------------------------------------------------------
// Two-level int8 GEMM.
// EPI 3: merged QKV — z<2: fused int8 quant (Q/K); z==2: fp16 C (V).
// EPI 4: per-chunk (per-head) A scales, fp32 C + bias (output projection).
// ---------------------------------------------------------------------------
#define GK 2048
#define NCH8 32
#define SSTG 32768
#define GS8_SMEM (3 * SSTG)

struct GArgs {
    const int8_t *B1, *B2;
    const float* sB;
    const float* bias;
    float* C;
    __half* Ch;
    int8_t *Q1, *Q2;
    float* SQ;
};

__device__ __forceinline__ void s8_load(
    const int8_t* __restrict__ A1, const int8_t* __restrict__ A2,
    const int8_t* __restrict__ B1, const int8_t* __restrict__ B2,
    int m0, int n0, int k0, uint32_t sb, int t)
{
#pragma unroll
    for (int i = 0; i < 2; i++) {
        int idx = t + i * 256, r = idx >> 2, c = idx & 3;
        uint32_t so = (uint32_t)(r * 64 + (((c ^ ((r >> 1) & 3))) << 4));
        size_t ga = (size_t)(m0 + r) * GK + k0 + c * 16;
        size_t gb = (size_t)(n0 + r) * GK + k0 + c * 16;
        cp_async16(sb +          so, A1 + ga);
        cp_async16(sb +  8192u + so, A2 + ga);
        cp_async16(sb + 16384u + so, B1 + gb);
        cp_async16(sb + 24576u + so, B2 + gb);
    }
}

template<int EPI>
__global__ __launch_bounds__(256, 1) void gemm_s8(
    const int8_t* __restrict__ A1, const int8_t* __restrict__ A2,
    const float* __restrict__ sA, GArgs a0, GArgs a1, GArgs a2)
{
    extern __shared__ char smem[];
    const uint32_t sbase = smem_u32(smem);
    const GArgs ga = (blockIdx.z == 0) ? a0 : (blockIdx.z == 1) ? a1 : a2;
    const int t = threadIdx.x, lane = t & 31, wid = t >> 5;
    const int warp_m = wid >> 2, warp_n = wid & 3;
    const int m0 = blockIdx.y * 128;
    const int n0 = blockIdx.x * 128;

    int a_row[4], b_row[2];
    uint32_t a_sw[4], b_sw[2];
#pragma unroll
    for (int mt = 0; mt < 4; mt++) {
        a_row[mt] = warp_m * 64 + mt * 16 + (lane & 15);
        a_sw[mt]  = (uint32_t)((a_row[mt] >> 1) & 3);
    }
#pragma unroll
    for (int pt = 0; pt < 2; pt++) {
        b_row[pt] = warp_n * 32 + pt * 16 + (lane & 7) + ((lane >> 4) & 1) * 8;
        b_sw[pt]  = (uint32_t)((b_row[pt] >> 1) & 3);
    }
    const uint32_t a_ch = (uint32_t)(lane >> 4);
    const uint32_t b_ch = (uint32_t)((lane >> 3) & 1);

    int acc1[4][4][4], acc2[4][4][4];
#pragma unroll
    for (int i = 0; i < 4; i++)
#pragma unroll
        for (int j = 0; j < 4; j++)
#pragma unroll
            for (int q = 0; q < 4; q++) { acc1[i][j][q] = 0; acc2[i][j][q] = 0; }

    float facc[4][4][4];
    if (EPI == 4) {
#pragma unroll
        for (int i = 0; i < 4; i++)
#pragma unroll
            for (int j = 0; j < 4; j++)
#pragma unroll
                for (int q = 0; q < 4; q++) facc[i][j][q] = 0.f;
    }

    s8_load(A1, A2, ga.B1, ga.B2, m0, n0, 0,   sbase,            t); CP_COMMIT();
    s8_load(A1, A2, ga.B1, ga.B2, m0, n0, 64,  sbase + SSTG,     t); CP_COMMIT();
    s8_load(A1, A2, ga.B1, ga.B2, m0, n0, 128, sbase + 2 * SSTG, t); CP_COMMIT();

    uint32_t stg = 0;
    for (int ch = 0; ch < NCH8; ch++) {
        CP_WAIT2();
        __syncthreads();
        const uint32_t sb = sbase + stg * SSTG;

#pragma unroll
        for (int s = 0; s < 2; s++) {
            uint32_t Af1[4][4], Af2[4][4];
            uint32_t Bf1[2][4], Bf2[2][4];
#pragma unroll
            for (int mt = 0; mt < 4; mt++) {
                uint32_t c = (uint32_t)(s * 2) + a_ch;
                uint32_t off = (uint32_t)(a_row[mt] * 64) + ((c ^ a_sw[mt]) << 4);
                ldm_x4(Af1[mt], sb + off);
                ldm_x4(Af2[mt], sb + 8192u + off);
            }
#pragma unroll
            for (int pt = 0; pt < 2; pt++) {
                uint32_t c = (uint32_t)(s * 2) + b_ch;
                uint32_t off = (uint32_t)(b_row[pt] * 64) + ((c ^ b_sw[pt]) << 4);
                ldm_x4(Bf1[pt], sb + 16384u + off);
                ldm_x4(Bf2[pt], sb + 24576u + off);
            }
#pragma unroll
            for (int mt = 0; mt < 4; mt++)
#pragma unroll
                for (int nt = 0; nt < 4; nt++) {
                    const int pt = nt >> 1, hl = (nt & 1) * 2;
                    mma_s8(acc1[mt][nt], Af1[mt], Bf1[pt][hl], Bf1[pt][hl+1]);
                    mma_s8(acc2[mt][nt], Af1[mt], Bf2[pt][hl], Bf2[pt][hl+1]);
                    mma_s8(acc2[mt][nt], Af2[mt], Bf1[pt][hl], Bf1[pt][hl+1]);
                }
        }

        if (EPI == 4) {
            // per-chunk (= per-head) dequant-accumulate into fp32
#pragma unroll
            for (int mt = 0; mt < 4; mt++) {
                const int r0g = m0 + warp_m * 64 + mt * 16 + (lane >> 2);
                const float sa0 = sA[(size_t)ch * M_ + r0g];
                const float sa1 = sA[(size_t)ch * M_ + r0g + 8];
#pragma unroll
                for (int nt = 0; nt < 4; nt++)
#pragma unroll
                    for (int e = 0; e < 4; e++) {
                        const float sa = (e >> 1) ? sa1 : sa0;
                        facc[mt][nt][e] += sa *
                            (float)(acc1[mt][nt][e] * 254 + acc2[mt][nt][e]);
                        acc1[mt][nt][e] = 0;
                        acc2[mt][nt][e] = 0;
                    }
            }
        }

        __syncthreads();
        if (ch + 3 < NCH8)
            s8_load(A1, A2, ga.B1, ga.B2, m0, n0, (ch + 3) * 64,
                    sbase + stg * SSTG, t);
        CP_COMMIT();
        stg = (stg == 2) ? 0 : stg + 1;
    }

    const float R = 1.f / 254.f;
    if (EPI == 4) {
#pragma unroll
        for (int mt = 0; mt < 4; mt++) {
            const int r0 = m0 + warp_m * 64 + mt * 16 + (lane >> 2);
#pragma unroll
            for (int nt = 0; nt < 4; nt++) {
                const int cc = n0 + warp_n * 32 + nt * 8 + (lane & 3) * 2;
                const float sb0 = ga.sB[cc] * R, sb1 = ga.sB[cc + 1] * R;
                const float bx = ga.bias[cc], by = ga.bias[cc + 1];
                float v0 = facc[mt][nt][0] * sb0 + bx;
                float v1 = facc[mt][nt][1] * sb1 + by;
                float v2 = facc[mt][nt][2] * sb0 + bx;
                float v3 = facc[mt][nt][3] * sb1 + by;
                *(float2*)(ga.C + (size_t)r0 * GK + cc)       = make_float2(v0, v1);
                *(float2*)(ga.C + (size_t)(r0 + 8) * GK + cc) = make_float2(v2, v3);
            }
        }
    } else if (EPI == 3 && blockIdx.z == 2) {
#pragma unroll
        for (int mt = 0; mt < 4; mt++) {
            const int r0 = m0 + warp_m * 64 + mt * 16 + (lane >> 2);
            const float sa0 = sA[r0], sa1 = sA[r0 + 8];
#pragma unroll
            for (int nt = 0; nt < 4; nt++) {
                const int cc = n0 + warp_n * 32 + nt * 8 + (lane & 3) * 2;
                const float sb0 = ga.sB[cc], sb1 = ga.sB[cc + 1];
                const float bx = ga.bias[cc], by = ga.bias[cc + 1];
                float v0 = ((float)acc1[mt][nt][0] + (float)acc2[mt][nt][0] * R) * (sa0 * sb0) + bx;
                float v1 = ((float)acc1[mt][nt][1] + (float)acc2[mt][nt][1] * R) * (sa0 * sb1) + by;
                float v2 = ((float)acc1[mt][nt][2] + (float)acc2[mt][nt][2] * R) * (sa1 * sb0) + bx;
                float v3 = ((float)acc1[mt][nt][3] + (float)acc2[mt][nt][3] * R) * (sa1 * sb1) + by;
                *(uint32_t*)(ga.Ch + (size_t)r0 * GK + cc)       = packh(v0, v1);
                *(uint32_t*)(ga.Ch + (size_t)(r0 + 8) * GK + cc) = packh(v2, v3);
            }
        }
    } else {
        // fused per-(row, 64-col head) two-level int8 quantization (Q/K)
        CP_WAIT0();
        __syncthreads();
        float* red = (float*)smem;      // 8 warps x 64 rows
        const int rbase = wid * 64;
#pragma unroll
        for (int mt = 0; mt < 4; mt++) {
            const int r0g = m0 + warp_m * 64 + mt * 16 + (lane >> 2);
            const float sa0 = sA[r0g], sa1 = sA[r0g + 8];
#pragma unroll
            for (int rr = 0; rr < 2; rr++) {
                const float sa = rr ? sa1 : sa0;
                float mx = 0.f;
#pragma unroll
                for (int nt = 0; nt < 4; nt++) {
                    const int cc = n0 + warp_n * 32 + nt * 8 + (lane & 3) * 2;
                    float v0 = ((float)acc1[mt][nt][rr*2]   + (float)acc2[mt][nt][rr*2]   * R)
                               * (sa * ga.sB[cc])     + ga.bias[cc];
                    float v1 = ((float)acc1[mt][nt][rr*2+1] + (float)acc2[mt][nt][rr*2+1] * R)
                               * (sa * ga.sB[cc + 1]) + ga.bias[cc + 1];
                    mx = fmaxf(mx, fmaxf(fabsf(v0), fabsf(v1)));
                }
                mx = fmaxf(mx, __shfl_xor_sync(~0u, mx, 1));
                mx = fmaxf(mx, __shfl_xor_sync(~0u, mx, 2));
                red[rbase + mt * 16 + rr * 8 + (lane >> 2)] = mx;
            }
        }
        __syncthreads();
        const int h = (n0 >> 6) + (warp_n >> 1);
#pragma unroll
        for (int mt = 0; mt < 4; mt++) {
            const int r0g = m0 + warp_m * 64 + mt * 16 + (lane >> 2);
            const float sa0 = sA[r0g], sa1 = sA[r0g + 8];
#pragma unroll
            for (int rr = 0; rr < 2; rr++) {
                const float sa = rr ? sa1 : sa0;
                const int idx = mt * 16 + rr * 8 + (lane >> 2);
                float m2 = fmaxf(red[rbase + idx], red[(rbase ^ 64) + idx]);
                m2 = fmaxf(m2, 1e-20f);
                const int grow = r0g + rr * 8;
                if ((lane & 3) == 0)
                    ga.SQ[(size_t)h * M_ + grow] = m2 * (1.f / 127.f);
                const float inv = 127.f / m2;
#pragma unroll
                for (int nt = 0; nt < 4; nt++) {
                    const int cc = n0 + warp_n * 32 + nt * 8 + (lane & 3) * 2;
                    float v0 = ((float)acc1[mt][nt][rr*2]   + (float)acc2[mt][nt][rr*2]   * R)
                               * (sa * ga.sB[cc])     + ga.bias[cc];
                    float v1 = ((float)acc1[mt][nt][rr*2+1] + (float)acc2[mt][nt][rr*2+1] * R)
                               * (sa * ga.sB[cc + 1]) + ga.bias[cc + 1];
                    float A0 = v0 * inv, A1v = v1 * inv;
                    float f0 = rintf(A0), f1 = rintf(A1v);
                    int i0 = (int)f0, i1 = (int)f1;
                    int r0v = (int)rintf((A0 - f0) * 254.f);
                    int r1v = (int)rintf((A1v - f1) * 254.f);
                    *(uint16_t*)(ga.Q1 + (size_t)grow * 2048 + cc) =
                        (uint16_t)((i0 & 0xff) | ((i1 & 0xff) << 8));
                    *(uint16_t*)(ga.Q2 + (size_t)grow * 2048 + cc) =
                        (uint16_t)((r0v & 0xff) | ((r1v & 0xff) << 8));
                }
            }
        }
    }
}

// ---------------------------------------------------------------------------
// Hybrid flash attention (causal): int8 two-level QK, fp16 P x fp16 V PV.
// Epilogue quantizes output directly to two-level int8 per (row, head).
// ---------------------------------------------------------------------------
#define FQT 128
#define FKT 64
#define STG_SZ 16384u
#define SCOFF 32768u
#define FA_SMEM 33280

__global__ __launch_bounds__(256, 2) void flash_hyb(
    const int8_t* __restrict__ q1g, const int8_t* __restrict__ q2g,
    const float* __restrict__ sqg,
    const int8_t* __restrict__ k1g, const int8_t* __restrict__ k2g,
    const float* __restrict__ skg,
    const __half* __restrict__ Vh,
    int8_t* __restrict__ a1o, int8_t* __restrict__ a2o,
    float* __restrict__ sa2)
{
    extern __shared__ char smem[];
    const uint32_t sb = smem_u32(smem);
    const int t = threadIdx.x, lane = t & 31, wid = t >> 5;
    const int qt = (int)gridDim.x - 1 - (int)blockIdx.x;   // heavy tiles first
    const int bh = blockIdx.y;
    const int b = bh >> 5, h = bh & 31;
    const int q0 = qt * FQT;
    const int qrow0 = b * S_ + q0;
    const int krow0 = b * S_;
    const int hoff = h * D_;
    const size_t vbase = ((size_t)b * S_) * E_ + hoff;
    const float* skh = skg + (size_t)h * M_ + b * S_;
    const float CEXP = SCALE_ * 1.4426950408889634f;
    const float CR = CEXP * (1.f / 254.f);
    const uint32_t HONES = 0x3C003C00u;   // fp16 {1, 1}

    // ---- stage Q (int8, both levels): 128 rows x 64B per level = 8K each ----
#pragma unroll
    for (int i = 0; i < 2; i++) {
        int idx = t + i * 256, r = idx >> 2, c = idx & 3;
        uint32_t so = (uint32_t)(r * 64 + ((c ^ ((r >> 1) & 3)) << 4));
        size_t g = (size_t)(qrow0 + r) * 2048 + hoff + c * 16;
        cp_async16(sb +         so, q1g + g);
        cp_async16(sb + 8192u + so, q2g + g);
    }
    CP_COMMIT(); CP_WAIT0();
    __syncthreads();

    uint32_t fq1[2][4], fq2[2][4];
#pragma unroll
    for (int kc = 0; kc < 2; kc++) {
        int row = wid * 16 + (lane & 15);
        uint32_t c = (uint32_t)(kc * 2 + (lane >> 4));
        uint32_t off = (uint32_t)(row * 64) + ((c ^ (uint32_t)((row >> 1) & 3)) << 4);
        ldm_x4(fq1[kc], sb + off);
        ldm_x4(fq2[kc], sb + 8192u + off);
    }
    float sqv[2];
#pragma unroll
    for (int rr = 0; rr < 2; rr++)
        sqv[rr] = sqg[(size_t)h * M_ + qrow0 + wid * 16 + (lane >> 2) + rr * 8];
    __syncthreads();   // Q area now reusable for KV stages

    // ---- precomputed ldmatrix smem offsets (stage-relative) ----
    uint32_t koff[2][2][2];
#pragma unroll
    for (int kc = 0; kc < 2; kc++)
#pragma unroll
        for (int kh = 0; kh < 2; kh++)
#pragma unroll
            for (int np2 = 0; np2 < 2; np2++) {
                int row = (kh * 2 + np2) * 16 + (lane & 7) + ((lane >> 4) & 1) * 8;
                uint32_t c = (uint32_t)(kc * 2 + ((lane >> 3) & 1));
                koff[kc][kh][np2] = (uint32_t)(row * 64)
                                  + ((c ^ (uint32_t)((row >> 1) & 3)) << 4);
            }
    uint32_t voff[4][4];
#pragma unroll
    for (int kc = 0; kc < 4; kc++)
#pragma unroll
        for (int ndp = 0; ndp < 4; ndp++) {
            int row = kc * 16 + (lane & 7) + ((lane >> 3) & 1) * 8;
            uint32_t c = (uint32_t)(2 * ndp) + (uint32_t)(lane >> 4);
            voff[kc][ndp] = 8192u + (uint32_t)(row * 128)
                          + ((c ^ (uint32_t)(row & 7)) << 4);
        }

    // ---- prefetch pointers ----
    const int rk_ = t >> 2, ck_ = t & 3;
    const uint32_t so_k = (uint32_t)(rk_ * 64 + ((ck_ ^ ((rk_ >> 1) & 3)) << 4));
    const int rv0 = t >> 3, cv_ = t & 7;
    const int rv1 = (t + 256) >> 3;
    const uint32_t so_v0 = (uint32_t)(rv0 * 128 + ((cv_ ^ (rv0 & 7)) << 4));
    const uint32_t so_v1 = (uint32_t)(rv1 * 128 + ((cv_ ^ (rv1 & 7)) << 4));
    const size_t gk_base = (size_t)(krow0 + rk_) * 2048 + hoff + ck_ * 16;
    const int8_t* gk1p = k1g + gk_base + (size_t)FKT * 2048;
    const int8_t* gk2p = k2g + gk_base + (size_t)FKT * 2048;
    const __half* gv0p = Vh + vbase + (size_t)(FKT + rv0) * E_ + cv_ * 8;
    const __half* gv1p = Vh + vbase + (size_t)(FKT + rv1) * E_ + cv_ * 8;
    const float* skp = skh + FKT + t * 4;
    const int mrow_base = q0 + wid * 16 + (lane >> 2);

    const int jmax = 2 * (qt + 1);
    {   // KV tile 0 -> stage 0
        cp_async16(sb +         so_k, k1g + gk_base);
        cp_async16(sb + 4096u + so_k, k2g + gk_base);
        if (t < 16) cp_async16(sb + SCOFF + t * 16u, skh + t * 4);
        cp_async16(sb + 8192u + so_v0, Vh + vbase + (size_t)rv0 * E_ + cv_ * 8);
        cp_async16(sb + 8192u + so_v1, Vh + vbase + (size_t)rv1 * E_ + cv_ * 8);
    }
    CP_COMMIT();

    float Oacc[8][4];
#pragma unroll
    for (int j = 0; j < 8; j++)
#pragma unroll
        for (int q = 0; q < 4; q++) Oacc[j][q] = 0.f;
    float lacc[4] = {0.f, 0.f, 0.f, 0.f};
    float m_i[2] = {-1e30f, -1e30f};

    for (int jt = 0; jt < jmax; jt++) {
        const int k0 = jt * FKT;
        __syncthreads();
        if (jt + 1 < jmax) {
            uint32_t st = (uint32_t)((jt + 1) & 1) * STG_SZ;
            cp_async16(sb + st +         so_k, gk1p);
            cp_async16(sb + st + 4096u + so_k, gk2p);
            if (t < 16)
                cp_async16(sb + SCOFF + (uint32_t)((jt + 1) & 1) * 256u + t * 16u, skp);
            cp_async16(sb + st + 8192u + so_v0, gv0p);
            cp_async16(sb + st + 8192u + so_v1, gv1p);
        }
        gk1p += FKT * 2048; gk2p += FKT * 2048;
        gv0p += (size_t)FKT * E_; gv1p += (size_t)FKT * E_;
        skp += FKT;
        CP_COMMIT(); CP_WAIT1();
        __syncthreads();
        const uint32_t st = sb + (uint32_t)(jt & 1) * STG_SZ;
        const float* sks = (const float*)(smem + SCOFF + (jt & 1) * 256);

        // ---- S = Q K^T (int8 two-level), dequant to exponent domain ----
        float sacc[8][4];
#pragma unroll
        for (int kh = 0; kh < 2; kh++) {
            int i1[4][4], i2[4][4];
#pragma unroll
            for (int j = 0; j < 4; j++)
#pragma unroll
                for (int q = 0; q < 4; q++) { i1[j][q] = 0; i2[j][q] = 0; }
#pragma unroll
            for (int kc = 0; kc < 2; kc++) {
                uint32_t bk1[2][4], bk2[2][4];
#pragma unroll
                for (int np2 = 0; np2 < 2; np2++) {
                    const uint32_t off = koff[kc][kh][np2];
                    ldm_x4(bk1[np2], st + off);
                    ldm_x4(bk2[np2], st + 4096u + off);
                }
#pragma unroll
                for (int np2 = 0; np2 < 2; np2++)
#pragma unroll
                    for (int nt2 = 0; nt2 < 2; nt2++) {
                        const int sl = np2 * 2 + nt2, hl = nt2 * 2;
                        mma_s8(i1[sl], fq1[kc], bk1[np2][hl], bk1[np2][hl+1]);
                        mma_s8(i2[sl], fq1[kc], bk2[np2][hl], bk2[np2][hl+1]);
                        mma_s8(i2[sl], fq2[kc], bk1[np2][hl], bk1[np2][hl+1]);
                    }
            }
#pragma unroll
            for (int sl = 0; sl < 4; sl++) {
                const int nt = kh * 4 + sl;
                const int c0 = nt * 8 + (lane & 3) * 2;
                const float kc0 = sks[c0] * CR, kc1 = sks[c0 + 1] * CR;
#pragma unroll
                for (int rr = 0; rr < 2; rr++) {
                    const float t0 = kc0 * sqv[rr], t1 = kc1 * sqv[rr];
                    sacc[nt][rr*2]   = t0 * (float)(i1[sl][rr*2]   * 254 + i2[sl][rr*2]);
                    sacc[nt][rr*2+1] = t1 * (float)(i1[sl][rr*2+1] * 254 + i2[sl][rr*2+1]);
                }
            }
        }

        // ---- causal mask (exponent domain) ----
        if (k0 + FKT - 1 > q0) {
#pragma unroll
            for (int nt = 0; nt < 8; nt++)
#pragma unroll
                for (int e = 0; e < 4; e++) {
                    int qrow = mrow_base + (e >> 1) * 8;
                    int kcol = k0 + nt * 8 + (lane & 3) * 2 + (e & 1);
                    if (kcol > qrow) sacc[nt][e] = -1e30f;
                }
        }

        // ---- online max + rescale ----
        float m_new[2], alpha[2];
#pragma unroll
        for (int rr = 0; rr < 2; rr++) {
            float mx = -1e30f;
#pragma unroll
            for (int nt = 0; nt < 8; nt++)
                mx = fmaxf(mx, fmaxf(sacc[nt][rr*2], sacc[nt][rr*2+1]));
            mx = fmaxf(mx, __shfl_xor_sync(0xffffffffu, mx, 1));
            mx = fmaxf(mx, __shfl_xor_sync(0xffffffffu, mx, 2));
            m_new[rr] = fmaxf(m_i[rr], mx);
            alpha[rr] = ex2(m_i[rr] - m_new[rr]);
            m_i[rr] = m_new[rr];
#pragma unroll
            for (int nd = 0; nd < 8; nd++) {
                Oacc[nd][rr*2]   *= alpha[rr];
                Oacc[nd][rr*2+1] *= alpha[rr];
            }
        }
        lacc[0] *= alpha[0]; lacc[1] *= alpha[0];
        lacc[2] *= alpha[1]; lacc[3] *= alpha[1];

        // ---- O += P V, l += P 1 (p via f16x2 ex2) ----
#pragma unroll
        for (int kc = 0; kc < 4; kc++) {
            uint32_t ph[4];
            ph[0] = ex2h2(packh(sacc[2*kc][0]   - m_new[0], sacc[2*kc][1]   - m_new[0]));
            ph[1] = ex2h2(packh(sacc[2*kc][2]   - m_new[1], sacc[2*kc][3]   - m_new[1]));
            ph[2] = ex2h2(packh(sacc[2*kc+1][0] - m_new[0], sacc[2*kc+1][1] - m_new[0]));
            ph[3] = ex2h2(packh(sacc[2*kc+1][2] - m_new[1], sacc[2*kc+1][3] - m_new[1]));
            mma_h(lacc, ph, HONES, HONES);
#pragma unroll
            for (int ndp = 0; ndp < 4; ndp++) {
                uint32_t bvh[4];
                ldm_x4t(bvh, st + voff[kc][ndp]);
#pragma unroll
                for (int nt2 = 0; nt2 < 2; nt2++) {
                    const int nd = ndp * 2 + nt2;
                    mma_h(Oacc[nd], ph, bvh[nt2*2], bvh[nt2*2+1]);
                }
            }
        }
    }

    // ---- epilogue: normalize, per-(row, head) two-level int8 quantize ----
#pragma unroll
    for (int rr = 0; rr < 2; rr++) {
        const int row = wid * 16 + (lane >> 2) + rr * 8;
        const int grow = qrow0 + row;
        const float inv = 1.f / lacc[rr * 2];
        float v[16];
        float mx = 0.f;
#pragma unroll
        for (int nd = 0; nd < 8; nd++) {
            v[nd*2]   = Oacc[nd][rr*2]   * inv;
            v[nd*2+1] = Oacc[nd][rr*2+1] * inv;
            mx = fmaxf(mx, fmaxf(fabsf(v[nd*2]), fabsf(v[nd*2+1])));
        }
        mx = fmaxf(mx, __shfl_xor_sync(0xffffffffu, mx, 1));
        mx = fmaxf(mx, __shfl_xor_sync(0xffffffffu, mx, 2));
        mx = fmaxf(mx, 1e-20f);
        if ((lane & 3) == 0)
            sa2[(size_t)h * M_ + grow] = mx * (1.f / 127.f);
        const float qs = 127.f / mx;
        const size_t rb = (size_t)grow * 2048 + hoff + (lane & 3) * 2;
#pragma unroll
        for (int nd = 0; nd < 8; nd++) {
            float A0 = v[nd*2] * qs, A1v = v[nd*2+1] * qs;
            float f0 = rintf(A0), f1 = rintf(A1v);
            int i0 = (int)f0, i1 = (int)f1;
            int r0v = (int)rintf((A0 - f0) * 254.f);
            int r1v = (int)rintf((A1v - f1) * 254.f);
            *(uint16_t*)(a1o + rb + nd * 8) =
                (uint16_t)((i0 & 0xff) | ((i1 & 0xff) << 8));
            *(uint16_t*)(a2o + rb + nd * 8) =
                (uint16_t)((r0v & 0xff) | ((r1v & 0xff) << 8));
        }
    }
}

// ---------------------------------------------------------------------------
extern "C" void kernel_launch(void* const* d_in, const int* in_sizes, int n_in,
                              void* d_out, int out_size)
{
    const float* x  = (const float*)d_in[0];
    const float* Wq = (const float*)d_in[1];
    const float* bq = (const float*)d_in[2];
    const float* Wk = (const float*)d_in[3];
    const float* bk = (const float*)d_in[4];
    const float* Wv = (const float*)d_in[5];
    const float* bv = (const float*)d_in[6];
    const float* Wo = (const float*)d_in[7];
    const float* bo = (const float*)d_in[8];
    float* out = (float*)d_out;

    int8_t *x1, *x2, *a1, *a2;
    int8_t *wq1, *wq2, *wk1, *wk2, *wv1, *wv2, *wo1, *wo2;
    int8_t *q1, *q2, *k1, *k2;
    float *sx, *sa2, *swq, *swk, *swv, *swo, *sq, *sk;
    __half *vh;
    cudaGetSymbolAddress((void**)&x1, g_x1);
    cudaGetSymbolAddress((void**)&x2, g_x2);
    cudaGetSymbolAddress((void**)&sx, g_sx);
    cudaGetSymbolAddress((void**)&a1, g_a1);
    cudaGetSymbolAddress((void**)&a2, g_a2);
    cudaGetSymbolAddress((void**)&sa2, g_sa2);
    cudaGetSymbolAddress((void**)&wq1, g_wq1);
    cudaGetSymbolAddress((void**)&wq2, g_wq2);
    cudaGetSymbolAddress((void**)&swq, g_swq);
    cudaGetSymbolAddress((void**)&wk1, g_wk1);
    cudaGetSymbolAddress((void**)&wk2, g_wk2);
    cudaGetSymbolAddress((void**)&swk, g_swk);
    cudaGetSymbolAddress((void**)&wv1, g_wv1);
    cudaGetSymbolAddress((void**)&wv2, g_wv2);
    cudaGetSymbolAddress((void**)&swv, g_swv);
    cudaGetSymbolAddress((void**)&wo1, g_wo1);
    cudaGetSymbolAddress((void**)&wo2, g_wo2);
    cudaGetSymbolAddress((void**)&swo, g_swo);
    cudaGetSymbolAddress((void**)&q1, g_q1);
    cudaGetSymbolAddress((void**)&q2, g_q2);
    cudaGetSymbolAddress((void**)&k1, g_k1);
    cudaGetSymbolAddress((void**)&k2, g_k2);
    cudaGetSymbolAddress((void**)&sq, g_sq);
    cudaGetSymbolAddress((void**)&sk, g_sk);
    cudaGetSymbolAddress((void**)&vh, g_vh);

    cudaFuncSetAttribute(gemm_s8<3>,
                         cudaFuncAttributeMaxDynamicSharedMemorySize, GS8_SMEM);
    cudaFuncSetAttribute(gemm_s8<4>,
                         cudaFuncAttributeMaxDynamicSharedMemorySize, GS8_SMEM);
    cudaFuncSetAttribute(flash_hyb,
                         cudaFuncAttributeMaxDynamicSharedMemorySize, FA_SMEM);

    RQArgs rx{x,  x1,  x2,  sx,  M_};
    RQArgs rq{Wq, wq1, wq2, swq, E_};
    RQArgs rk{Wk, wk1, wk2, swk, E_};
    RQArgs rv{Wv, wv1, wv2, swv, E_};
    RQArgs ro{Wo, wo1, wo2, swo, E_};
    rowquant5<<<dim3(M_, 5), 256>>>(rx, rq, rk, rv, ro);

    GArgs aq{wq1, wq2, swq, bq, nullptr, nullptr, q1, q2, sq};
    GArgs ak{wk1, wk2, swk, bk, nullptr, nullptr, k1, k2, sk};
    GArgs av{wv1, wv2, swv, bv, nullptr, vh, nullptr, nullptr, nullptr};
    GArgs ao{wo1, wo2, swo, bo, out, nullptr, nullptr, nullptr, nullptr};

    dim3 gqkv(E_ / 128, M_ / 128, 3);
    gemm_s8<3><<<gqkv, 256, GS8_SMEM>>>(x1, x2, sx, aq, ak, av);

    dim3 ga(S_ / FQT, B_ * H_);     // (16, 64)
    flash_hyb<<<ga, 256, FA_SMEM>>>(q1, q2, sq, k1, k2, sk, vh, a1, a2, sa2);

    dim3 go(E_ / 128, M_ / 128, 1);
    gemm_s8<4><<<go, 256, GS8_SMEM>>>(a1, a2, sa2, ao, ao, ao);
}

// round 17
// speedup vs baseline: 1.0715x; 1.0715x over previous
#include <cuda_runtime.h>
#include <cuda_bf16.h>
#include <cuda_fp16.h>
#include <cstdint>
#include <math.h>

#define B_ 2
#define S_ 2048
#define E_ 2048
#define H_ 32
#define D_ 64
#define M_ (B_*S_)
#define SCALE_ 0.125f

// ---------------- scratch ----------------
static __device__ __align__(128) int8_t g_x1[(size_t)M_ * E_];
static __device__ __align__(128) int8_t g_x2[(size_t)M_ * E_];
static __device__ __align__(128) float  g_sx[M_];
static __device__ __align__(128) int8_t g_a1[(size_t)M_ * E_];
static __device__ __align__(128) int8_t g_a2[(size_t)M_ * E_];
static __device__ __align__(128) float  g_sa[M_];
static __device__ __align__(128) __half g_attn[(size_t)M_ * E_];

static __device__ __align__(128) int8_t g_wq1[(size_t)E_ * E_];
static __device__ __align__(128) int8_t g_wq2[(size_t)E_ * E_];
static __device__ __align__(128) float  g_swq[E_];
static __device__ __align__(128) int8_t g_wk1[(size_t)E_ * E_];
static __device__ __align__(128) int8_t g_wk2[(size_t)E_ * E_];
static __device__ __align__(128) float  g_swk[E_];
static __device__ __align__(128) int8_t g_wv1[(size_t)E_ * E_];
static __device__ __align__(128) int8_t g_wv2[(size_t)E_ * E_];
static __device__ __align__(128) float  g_swv[E_];
static __device__ __align__(128) int8_t g_wo1[(size_t)E_ * E_];
static __device__ __align__(128) int8_t g_wo2[(size_t)E_ * E_];
static __device__ __align__(128) float  g_swo[E_];

static __device__ __align__(128) int8_t g_q1[(size_t)M_ * E_];
static __device__ __align__(128) int8_t g_q2[(size_t)M_ * E_];
static __device__ __align__(128) int8_t g_k1[(size_t)M_ * E_];
static __device__ __align__(128) int8_t g_k2[(size_t)M_ * E_];
static __device__ __align__(128) float  g_sq[(size_t)H_ * M_];
static __device__ __align__(128) float  g_sk[(size_t)H_ * M_];

static __device__ __align__(128) __half g_vh[(size_t)M_ * E_];

// ---------------- helpers ----------------
__device__ __forceinline__ uint32_t smem_u32(const void* p) {
    uint32_t a;
    asm("{ .reg .u64 t; cvta.to.shared.u64 t, %1; cvt.u32.u64 %0, t; }"
        : "=r"(a) : "l"(p));
    return a;
}
__device__ __forceinline__ void cp_async16(uint32_t saddr, const void* gaddr) {
    asm volatile("cp.async.cg.shared.global [%0], [%1], 16;\n"
                 :: "r"(saddr), "l"(gaddr));
}
#define CP_COMMIT() asm volatile("cp.async.commit_group;\n" ::: "memory")
#define CP_WAIT0()  asm volatile("cp.async.wait_group 0;\n" ::: "memory")
#define CP_WAIT1()  asm volatile("cp.async.wait_group 1;\n" ::: "memory")
#define CP_WAIT2()  asm volatile("cp.async.wait_group 2;\n" ::: "memory")

__device__ __forceinline__ void ldm_x4(uint32_t* r, uint32_t addr) {
    asm volatile("ldmatrix.sync.aligned.m8n8.x4.shared.b16 {%0,%1,%2,%3}, [%4];"
                 : "=r"(r[0]), "=r"(r[1]), "=r"(r[2]), "=r"(r[3]) : "r"(addr));
}
__device__ __forceinline__ void ldm_x4t(uint32_t* r, uint32_t addr) {
    asm volatile("ldmatrix.sync.aligned.m8n8.x4.trans.shared.b16 {%0,%1,%2,%3}, [%4];"
                 : "=r"(r[0]), "=r"(r[1]), "=r"(r[2]), "=r"(r[3]) : "r"(addr));
}
__device__ __forceinline__ void mma_h(float* d, const uint32_t* a,
                                      uint32_t b0, uint32_t b1) {
    asm volatile(
        "mma.sync.aligned.m16n8k16.row.col.f32.f16.f16.f32 "
        "{%0,%1,%2,%3}, {%4,%5,%6,%7}, {%8,%9}, {%0,%1,%2,%3};"
        : "+f"(d[0]), "+f"(d[1]), "+f"(d[2]), "+f"(d[3])
        : "r"(a[0]), "r"(a[1]), "r"(a[2]), "r"(a[3]), "r"(b0), "r"(b1));
}
__device__ __forceinline__ void mma_s8(int* d, const uint32_t* a,
                                       uint32_t b0, uint32_t b1) {
    asm volatile(
        "mma.sync.aligned.m16n8k32.row.col.s32.s8.s8.s32 "
        "{%0,%1,%2,%3}, {%4,%5,%6,%7}, {%8,%9}, {%0,%1,%2,%3};"
        : "+r"(d[0]), "+r"(d[1]), "+r"(d[2]), "+r"(d[3])
        : "r"(a[0]), "r"(a[1]), "r"(a[2]), "r"(a[3]), "r"(b0), "r"(b1));
}
__device__ __forceinline__ uint32_t packh(float lo, float hi) {
    uint32_t d;
    asm("cvt.rn.f16x2.f32 %0, %1, %2;" : "=r"(d) : "f"(hi), "f"(lo));
    return d;
}
__device__ __forceinline__ uint32_t ex2h2(uint32_t x) {
    uint32_t y;
    asm("ex2.approx.f16x2 %0, %1;" : "=r"(y) : "r"(x));
    return y;
}
__device__ __forceinline__ float ex2(float x) {
    float y; asm("ex2.approx.f32 %0, %1;" : "=f"(y) : "f"(x)); return y;
}

// ---------------------------------------------------------------------------
// Row-wise two-level int8 quantization over 2048-col rows (fp32 source).
// ---------------------------------------------------------------------------
struct RQArgs { const float* src; int8_t* q1; int8_t* q2; float* s; int rows; };

__device__ __forceinline__ void rowquant_core(
    float* vv, int8_t* __restrict__ q1, int8_t* __restrict__ q2,
    float* __restrict__ s, int row, int t, float* wmax)
{
    float m = 0.f;
#pragma unroll
    for (int j = 0; j < 8; j++) m = fmaxf(m, fabsf(vv[j]));
#pragma unroll
    for (int o = 16; o; o >>= 1) m = fmaxf(m, __shfl_xor_sync(~0u, m, o));
    if ((t & 31) == 0) wmax[t >> 5] = m;
    __syncthreads();
    float mm = wmax[0];
#pragma unroll
    for (int i = 1; i < 8; i++) mm = fmaxf(mm, wmax[i]);
    mm = fmaxf(mm, 1e-20f);
    if (t == 0) s[row] = mm * (1.f / 127.f);
    const float inv = 127.f / mm;

    uint32_t p1[2] = {0, 0}, p2[2] = {0, 0};
#pragma unroll
    for (int j = 0; j < 8; j++) {
        float xs = vv[j] * inv;
        float qf = rintf(xs);
        float rf = rintf((xs - qf) * 254.f);
        int iq = (int)qf, ir = (int)rf;
        p1[j >> 2] |= (uint32_t)(iq & 0xff) << ((j & 3) * 8);
        p2[j >> 2] |= (uint32_t)(ir & 0xff) << ((j & 3) * 8);
    }
    ((uint32_t*)q1)[row * 512 + t * 2]     = p1[0];
    ((uint32_t*)q1)[row * 512 + t * 2 + 1] = p1[1];
    ((uint32_t*)q2)[row * 512 + t * 2]     = p2[0];
    ((uint32_t*)q2)[row * 512 + t * 2 + 1] = p2[1];
}

__global__ __launch_bounds__(256) void rowquant5(
    RQArgs a0, RQArgs a1, RQArgs a2, RQArgs a3, RQArgs a4)
{
    __shared__ float wmax[8];
    RQArgs a = (blockIdx.y == 0) ? a0 : (blockIdx.y == 1) ? a1
             : (blockIdx.y == 2) ? a2 : (blockIdx.y == 3) ? a3 : a4;
    if ((int)blockIdx.x >= a.rows) return;
    const int row = blockIdx.x, t = threadIdx.x;
    const float* xr = a.src + (size_t)row * 2048 + t * 8;
    float4 v0 = ((const float4*)xr)[0];
    float4 v1 = ((const float4*)xr)[1];
    float vv[8] = {v0.x, v0.y, v0.z, v0.w, v1.x, v1.y, v1.z, v1.w};
    rowquant_core(vv, a.q1, a.q2, a.s, row, t, wmax);
}

// fp16-source row quantization (attention output)
__global__ __launch_bounds__(256) void rowquant_h(
    const __half* __restrict__ x, int8_t* __restrict__ q1,
    int8_t* __restrict__ q2, float* __restrict__ s)
{
    __shared__ float wmax[8];
    const int row = blockIdx.x, t = threadIdx.x;
    uint4 u = *(const uint4*)(x + (size_t)row * 2048 + t * 8);
    float vv[8];
    {
        __half2 h;
        h = *(__half2*)&u.x; float2 f = __half22float2(h); vv[0] = f.x; vv[1] = f.y;
        h = *(__half2*)&u.y; f = __half22float2(h); vv[2] = f.x; vv[3] = f.y;
        h = *(__half2*)&u.z; f = __half22float2(h); vv[4] = f.x; vv[5] = f.y;
        h = *(__half2*)&u.w; f = __half22float2(h); vv[6] = f.x; vv[7] = f.y;
    }
    rowquant_core(vv, q1, q2, s, row, t, wmax);
}

// ---------------------------------------------------------------------------
// Two-level int8 GEMM.
// EPI 0: fp32 C + bias.
// EPI 3: merged QKV — z<2: fused int8 quant (Q/K); z==2: fp16 C (V).
// ---------------------------------------------------------------------------
#define GK 2048
#define NCH8 32
#define SSTG 32768
#define GS8_SMEM (3 * SSTG)

struct GArgs {
    const int8_t *B1, *B2;
    const float* sB;
    const float* bias;
    float* C;
    __half* Ch;
    int8_t *Q1, *Q2;
    float* SQ;
};

__device__ __forceinline__ void s8_load(
    const int8_t* __restrict__ A1, const int8_t* __restrict__ A2,
    const int8_t* __restrict__ B1, const int8_t* __restrict__ B2,
    int m0, int n0, int k0, uint32_t sb, int t)
{
#pragma unroll
    for (int i = 0; i < 2; i++) {
        int idx = t + i * 256, r = idx >> 2, c = idx & 3;
        uint32_t so = (uint32_t)(r * 64 + (((c ^ ((r >> 1) & 3))) << 4));
        size_t ga = (size_t)(m0 + r) * GK + k0 + c * 16;
        size_t gb = (size_t)(n0 + r) * GK + k0 + c * 16;
        cp_async16(sb +          so, A1 + ga);
        cp_async16(sb +  8192u + so, A2 + ga);
        cp_async16(sb + 16384u + so, B1 + gb);
        cp_async16(sb + 24576u + so, B2 + gb);
    }
}

template<int EPI>
__global__ __launch_bounds__(256, 1) void gemm_s8(
    const int8_t* __restrict__ A1, const int8_t* __restrict__ A2,
    const float* __restrict__ sA, GArgs a0, GArgs a1, GArgs a2)
{
    extern __shared__ char smem[];
    const uint32_t sbase = smem_u32(smem);
    const GArgs ga = (blockIdx.z == 0) ? a0 : (blockIdx.z == 1) ? a1 : a2;
    const int t = threadIdx.x, lane = t & 31, wid = t >> 5;
    const int warp_m = wid >> 2, warp_n = wid & 3;
    const int m0 = blockIdx.y * 128;
    const int n0 = blockIdx.x * 128;

    int a_row[4], b_row[2];
    uint32_t a_sw[4], b_sw[2];
#pragma unroll
    for (int mt = 0; mt < 4; mt++) {
        a_row[mt] = warp_m * 64 + mt * 16 + (lane & 15);
        a_sw[mt]  = (uint32_t)((a_row[mt] >> 1) & 3);
    }
#pragma unroll
    for (int pt = 0; pt < 2; pt++) {
        b_row[pt] = warp_n * 32 + pt * 16 + (lane & 7) + ((lane >> 4) & 1) * 8;
        b_sw[pt]  = (uint32_t)((b_row[pt] >> 1) & 3);
    }
    const uint32_t a_ch = (uint32_t)(lane >> 4);
    const uint32_t b_ch = (uint32_t)((lane >> 3) & 1);

    int acc1[4][4][4], acc2[4][4][4];
#pragma unroll
    for (int i = 0; i < 4; i++)
#pragma unroll
        for (int j = 0; j < 4; j++)
#pragma unroll
            for (int q = 0; q < 4; q++) { acc1[i][j][q] = 0; acc2[i][j][q] = 0; }

    s8_load(A1, A2, ga.B1, ga.B2, m0, n0, 0,   sbase,            t); CP_COMMIT();
    s8_load(A1, A2, ga.B1, ga.B2, m0, n0, 64,  sbase + SSTG,     t); CP_COMMIT();
    s8_load(A1, A2, ga.B1, ga.B2, m0, n0, 128, sbase + 2 * SSTG, t); CP_COMMIT();

    uint32_t stg = 0;
    for (int ch = 0; ch < NCH8; ch++) {
        CP_WAIT2();
        __syncthreads();
        const uint32_t sb = sbase + stg * SSTG;

#pragma unroll
        for (int s = 0; s < 2; s++) {
            uint32_t Af1[4][4], Af2[4][4];
            uint32_t Bf1[2][4], Bf2[2][4];
#pragma unroll
            for (int mt = 0; mt < 4; mt++) {
                uint32_t c = (uint32_t)(s * 2) + a_ch;
                uint32_t off = (uint32_t)(a_row[mt] * 64) + ((c ^ a_sw[mt]) << 4);
                ldm_x4(Af1[mt], sb + off);
                ldm_x4(Af2[mt], sb + 8192u + off);
            }
#pragma unroll
            for (int pt = 0; pt < 2; pt++) {
                uint32_t c = (uint32_t)(s * 2) + b_ch;
                uint32_t off = (uint32_t)(b_row[pt] * 64) + ((c ^ b_sw[pt]) << 4);
                ldm_x4(Bf1[pt], sb + 16384u + off);
                ldm_x4(Bf2[pt], sb + 24576u + off);
            }
#pragma unroll
            for (int mt = 0; mt < 4; mt++)
#pragma unroll
                for (int nt = 0; nt < 4; nt++) {
                    const int pt = nt >> 1, hl = (nt & 1) * 2;
                    mma_s8(acc1[mt][nt], Af1[mt], Bf1[pt][hl], Bf1[pt][hl+1]);
                    mma_s8(acc2[mt][nt], Af1[mt], Bf2[pt][hl], Bf2[pt][hl+1]);
                    mma_s8(acc2[mt][nt], Af2[mt], Bf1[pt][hl], Bf1[pt][hl+1]);
                }
        }
        __syncthreads();
        if (ch + 3 < NCH8)
            s8_load(A1, A2, ga.B1, ga.B2, m0, n0, (ch + 3) * 64,
                    sbase + stg * SSTG, t);
        CP_COMMIT();
        stg = (stg == 2) ? 0 : stg + 1;
    }

    const float R = 1.f / 254.f;
    if (EPI == 0 || (EPI == 3 && blockIdx.z == 2)) {
#pragma unroll
        for (int mt = 0; mt < 4; mt++) {
            const int r0 = m0 + warp_m * 64 + mt * 16 + (lane >> 2);
            const float sa0 = sA[r0], sa1 = sA[r0 + 8];
#pragma unroll
            for (int nt = 0; nt < 4; nt++) {
                const int cc = n0 + warp_n * 32 + nt * 8 + (lane & 3) * 2;
                const float sb0 = ga.sB[cc], sb1 = ga.sB[cc + 1];
                const float bx = ga.bias[cc], by = ga.bias[cc + 1];
                float v0 = ((float)acc1[mt][nt][0] + (float)acc2[mt][nt][0] * R) * (sa0 * sb0) + bx;
                float v1 = ((float)acc1[mt][nt][1] + (float)acc2[mt][nt][1] * R) * (sa0 * sb1) + by;
                float v2 = ((float)acc1[mt][nt][2] + (float)acc2[mt][nt][2] * R) * (sa1 * sb0) + bx;
                float v3 = ((float)acc1[mt][nt][3] + (float)acc2[mt][nt][3] * R) * (sa1 * sb1) + by;
                if (EPI == 0) {
                    *(float2*)(ga.C + (size_t)r0 * GK + cc)       = make_float2(v0, v1);
                    *(float2*)(ga.C + (size_t)(r0 + 8) * GK + cc) = make_float2(v2, v3);
                } else {
                    *(uint32_t*)(ga.Ch + (size_t)r0 * GK + cc)       = packh(v0, v1);
                    *(uint32_t*)(ga.Ch + (size_t)(r0 + 8) * GK + cc) = packh(v2, v3);
                }
            }
        }
    } else {
        // fused per-(row, 64-col head) two-level int8 quantization (Q/K)
        CP_WAIT0();
        __syncthreads();
        float* red = (float*)smem;      // 8 warps x 64 rows
        const int rbase = wid * 64;
#pragma unroll
        for (int mt = 0; mt < 4; mt++) {
            const int r0g = m0 + warp_m * 64 + mt * 16 + (lane >> 2);
            const float sa0 = sA[r0g], sa1 = sA[r0g + 8];
#pragma unroll
            for (int rr = 0; rr < 2; rr++) {
                const float sa = rr ? sa1 : sa0;
                float mx = 0.f;
#pragma unroll
                for (int nt = 0; nt < 4; nt++) {
                    const int cc = n0 + warp_n * 32 + nt * 8 + (lane & 3) * 2;
                    float v0 = ((float)acc1[mt][nt][rr*2]   + (float)acc2[mt][nt][rr*2]   * R)
                               * (sa * ga.sB[cc])     + ga.bias[cc];
                    float v1 = ((float)acc1[mt][nt][rr*2+1] + (float)acc2[mt][nt][rr*2+1] * R)
                               * (sa * ga.sB[cc + 1]) + ga.bias[cc + 1];
                    mx = fmaxf(mx, fmaxf(fabsf(v0), fabsf(v1)));
                }
                mx = fmaxf(mx, __shfl_xor_sync(~0u, mx, 1));
                mx = fmaxf(mx, __shfl_xor_sync(~0u, mx, 2));
                red[rbase + mt * 16 + rr * 8 + (lane >> 2)] = mx;
            }
        }
        __syncthreads();
        const int h = (n0 >> 6) + (warp_n >> 1);
#pragma unroll
        for (int mt = 0; mt < 4; mt++) {
            const int r0g = m0 + warp_m * 64 + mt * 16 + (lane >> 2);
            const float sa0 = sA[r0g], sa1 = sA[r0g + 8];
#pragma unroll
            for (int rr = 0; rr < 2; rr++) {
                const float sa = rr ? sa1 : sa0;
                const int idx = mt * 16 + rr * 8 + (lane >> 2);
                float m2 = fmaxf(red[rbase + idx], red[(rbase ^ 64) + idx]);
                m2 = fmaxf(m2, 1e-20f);
                const int grow = r0g + rr * 8;
                if ((lane & 3) == 0)
                    ga.SQ[(size_t)h * M_ + grow] = m2 * (1.f / 127.f);
                const float inv = 127.f / m2;
#pragma unroll
                for (int nt = 0; nt < 4; nt++) {
                    const int cc = n0 + warp_n * 32 + nt * 8 + (lane & 3) * 2;
                    float v0 = ((float)acc1[mt][nt][rr*2]   + (float)acc2[mt][nt][rr*2]   * R)
                               * (sa * ga.sB[cc])     + ga.bias[cc];
                    float v1 = ((float)acc1[mt][nt][rr*2+1] + (float)acc2[mt][nt][rr*2+1] * R)
                               * (sa * ga.sB[cc + 1]) + ga.bias[cc + 1];
                    float A0 = v0 * inv, A1v = v1 * inv;
                    float f0 = rintf(A0), f1 = rintf(A1v);
                    int i0 = (int)f0, i1 = (int)f1;
                    int r0v = (int)rintf((A0 - f0) * 254.f);
                    int r1v = (int)rintf((A1v - f1) * 254.f);
                    *(uint16_t*)(ga.Q1 + (size_t)grow * 2048 + cc) =
                        (uint16_t)((i0 & 0xff) | ((i1 & 0xff) << 8));
                    *(uint16_t*)(ga.Q2 + (size_t)grow * 2048 + cc) =
                        (uint16_t)((r0v & 0xff) | ((r1v & 0xff) << 8));
                }
            }
        }
    }
}

// ---------------------------------------------------------------------------
// Hybrid flash attention (causal): int8 two-level QK, fp16 P x fp16 V PV.
// Epilogue stores fp16 attention output.
// ---------------------------------------------------------------------------
#define FQT 128
#define FKT 64
#define STG_SZ 16384u
#define SCOFF 32768u
#define FA_SMEM 33280

__global__ __launch_bounds__(256, 2) void flash_hyb(
    const int8_t* __restrict__ q1g, const int8_t* __restrict__ q2g,
    const float* __restrict__ sqg,
    const int8_t* __restrict__ k1g, const int8_t* __restrict__ k2g,
    const float* __restrict__ skg,
    const __half* __restrict__ Vh,
    __half* __restrict__ O)
{
    extern __shared__ char smem[];
    const uint32_t sb = smem_u32(smem);
    const int t = threadIdx.x, lane = t & 31, wid = t >> 5;
    const int qt = (int)gridDim.x - 1 - (int)blockIdx.x;   // heavy tiles first
    const int bh = blockIdx.y;
    const int b = bh >> 5, h = bh & 31;
    const int q0 = qt * FQT;
    const int qrow0 = b * S_ + q0;
    const int krow0 = b * S_;
    const int hoff = h * D_;
    const size_t vbase = ((size_t)b * S_) * E_ + hoff;
    const float* skh = skg + (size_t)h * M_ + b * S_;
    const float CEXP = SCALE_ * 1.4426950408889634f;
    const float CR = CEXP * (1.f / 254.f);
    const uint32_t HONES = 0x3C003C00u;   // fp16 {1, 1}

    // ---- stage Q (int8, both levels): 128 rows x 64B per level ----
#pragma unroll
    for (int i = 0; i < 2; i++) {
        int idx = t + i * 256, r = idx >> 2, c = idx & 3;
        uint32_t so = (uint32_t)(r * 64 + ((c ^ ((r >> 1) & 3)) << 4));
        size_t g = (size_t)(qrow0 + r) * 2048 + hoff + c * 16;
        cp_async16(sb +         so, q1g + g);
        cp_async16(sb + 8192u + so, q2g + g);
    }
    CP_COMMIT(); CP_WAIT0();
    __syncthreads();

    uint32_t fq1[2][4], fq2[2][4];
#pragma unroll
    for (int kc = 0; kc < 2; kc++) {
        int row = wid * 16 + (lane & 15);
        uint32_t c = (uint32_t)(kc * 2 + (lane >> 4));
        uint32_t off = (uint32_t)(row * 64) + ((c ^ (uint32_t)((row >> 1) & 3)) << 4);
        ldm_x4(fq1[kc], sb + off);
        ldm_x4(fq2[kc], sb + 8192u + off);
    }
    float sqv[2];
#pragma unroll
    for (int rr = 0; rr < 2; rr++)
        sqv[rr] = sqg[(size_t)h * M_ + qrow0 + wid * 16 + (lane >> 2) + rr * 8];
    __syncthreads();   // Q area now reusable for KV stages

    // ---- precomputed ldmatrix smem offsets ----
    uint32_t koff[2][2][2];
#pragma unroll
    for (int kc = 0; kc < 2; kc++)
#pragma unroll
        for (int kh = 0; kh < 2; kh++)
#pragma unroll
            for (int np2 = 0; np2 < 2; np2++) {
                int row = (kh * 2 + np2) * 16 + (lane & 7) + ((lane >> 4) & 1) * 8;
                uint32_t c = (uint32_t)(kc * 2 + ((lane >> 3) & 1));
                koff[kc][kh][np2] = (uint32_t)(row * 64)
                                  + ((c ^ (uint32_t)((row >> 1) & 3)) << 4);
            }
    uint32_t voff[4][4];
#pragma unroll
    for (int kc = 0; kc < 4; kc++)
#pragma unroll
        for (int ndp = 0; ndp < 4; ndp++) {
            int row = kc * 16 + (lane & 7) + ((lane >> 3) & 1) * 8;
            uint32_t c = (uint32_t)(2 * ndp) + (uint32_t)(lane >> 4);
            voff[kc][ndp] = 8192u + (uint32_t)(row * 128)
                          + ((c ^ (uint32_t)(row & 7)) << 4);
        }

    // ---- prefetch pointers ----
    const int rk_ = t >> 2, ck_ = t & 3;
    const uint32_t so_k = (uint32_t)(rk_ * 64 + ((ck_ ^ ((rk_ >> 1) & 3)) << 4));
    const int rv0 = t >> 3, cv_ = t & 7;
    const int rv1 = (t + 256) >> 3;
    const uint32_t so_v0 = (uint32_t)(rv0 * 128 + ((cv_ ^ (rv0 & 7)) << 4));
    const uint32_t so_v1 = (uint32_t)(rv1 * 128 + ((cv_ ^ (rv1 & 7)) << 4));
    const size_t gk_base = (size_t)(krow0 + rk_) * 2048 + hoff + ck_ * 16;
    const int8_t* gk1p = k1g + gk_base + (size_t)FKT * 2048;
    const int8_t* gk2p = k2g + gk_base + (size_t)FKT * 2048;
    const __half* gv0p = Vh + vbase + (size_t)(FKT + rv0) * E_ + cv_ * 8;
    const __half* gv1p = Vh + vbase + (size_t)(FKT + rv1) * E_ + cv_ * 8;
    const float* skp = skh + FKT + t * 4;
    const int mrow_base = q0 + wid * 16 + (lane >> 2);

    const int jmax = 2 * (qt + 1);
    {   // KV tile 0 -> stage 0
        cp_async16(sb +         so_k, k1g + gk_base);
        cp_async16(sb + 4096u + so_k, k2g + gk_base);
        if (t < 16) cp_async16(sb + SCOFF + t * 16u, skh + t * 4);
        cp_async16(sb + 8192u + so_v0, Vh + vbase + (size_t)rv0 * E_ + cv_ * 8);
        cp_async16(sb + 8192u + so_v1, Vh + vbase + (size_t)rv1 * E_ + cv_ * 8);
    }
    CP_COMMIT();

    float Oacc[8][4];
#pragma unroll
    for (int j = 0; j < 8; j++)
#pragma unroll
        for (int q = 0; q < 4; q++) Oacc[j][q] = 0.f;
    float lacc[4] = {0.f, 0.f, 0.f, 0.f};
    float m_i[2] = {-1e30f, -1e30f};

    for (int jt = 0; jt < jmax; jt++) {
        const int k0 = jt * FKT;
        __syncthreads();
        if (jt + 1 < jmax) {
            uint32_t st = (uint32_t)((jt + 1) & 1) * STG_SZ;
            cp_async16(sb + st +         so_k, gk1p);
            cp_async16(sb + st + 4096u + so_k, gk2p);
            if (t < 16)
                cp_async16(sb + SCOFF + (uint32_t)((jt + 1) & 1) * 256u + t * 16u, skp);
            cp_async16(sb + st + 8192u + so_v0, gv0p);
            cp_async16(sb + st + 8192u + so_v1, gv1p);
        }
        gk1p += FKT * 2048; gk2p += FKT * 2048;
        gv0p += (size_t)FKT * E_; gv1p += (size_t)FKT * E_;
        skp += FKT;
        CP_COMMIT(); CP_WAIT1();
        __syncthreads();
        const uint32_t st = sb + (uint32_t)(jt & 1) * STG_SZ;
        const float* sks = (const float*)(smem + SCOFF + (jt & 1) * 256);

        // ---- S = Q K^T (int8 two-level), dequant to exponent domain ----
        float sacc[8][4];
#pragma unroll
        for (int kh = 0; kh < 2; kh++) {
            int i1[4][4], i2[4][4];
#pragma unroll
            for (int j = 0; j < 4; j++)
#pragma unroll
                for (int q = 0; q < 4; q++) { i1[j][q] = 0; i2[j][q] = 0; }
#pragma unroll
            for (int kc = 0; kc < 2; kc++) {
                uint32_t bk1[2][4], bk2[2][4];
#pragma unroll
                for (int np2 = 0; np2 < 2; np2++) {
                    const uint32_t off = koff[kc][kh][np2];
                    ldm_x4(bk1[np2], st + off);
                    ldm_x4(bk2[np2], st + 4096u + off);
                }
#pragma unroll
                for (int np2 = 0; np2 < 2; np2++)
#pragma unroll
                    for (int nt2 = 0; nt2 < 2; nt2++) {
                        const int sl = np2 * 2 + nt2, hl = nt2 * 2;
                        mma_s8(i1[sl], fq1[kc], bk1[np2][hl], bk1[np2][hl+1]);
                        mma_s8(i2[sl], fq1[kc], bk2[np2][hl], bk2[np2][hl+1]);
                        mma_s8(i2[sl], fq2[kc], bk1[np2][hl], bk1[np2][hl+1]);
                    }
            }
#pragma unroll
            for (int sl = 0; sl < 4; sl++) {
                const int nt = kh * 4 + sl;
                const int c0 = nt * 8 + (lane & 3) * 2;
                const float kc0 = sks[c0] * CR, kc1 = sks[c0 + 1] * CR;
#pragma unroll
                for (int rr = 0; rr < 2; rr++) {
                    const float t0 = kc0 * sqv[rr], t1 = kc1 * sqv[rr];
                    sacc[nt][rr*2]   = t0 * (float)(i1[sl][rr*2]   * 254 + i2[sl][rr*2]);
                    sacc[nt][rr*2+1] = t1 * (float)(i1[sl][rr*2+1] * 254 + i2[sl][rr*2+1]);
                }
            }
        }

        // ---- causal mask (exponent domain) ----
        if (k0 + FKT - 1 > q0) {
#pragma unroll
            for (int nt = 0; nt < 8; nt++)
#pragma unroll
                for (int e = 0; e < 4; e++) {
                    int qrow = mrow_base + (e >> 1) * 8;
                    int kcol = k0 + nt * 8 + (lane & 3) * 2 + (e & 1);
                    if (kcol > qrow) sacc[nt][e] = -1e30f;
                }
        }

        // ---- online max + rescale ----
        float m_new[2], alpha[2];
#pragma unroll
        for (int rr = 0; rr < 2; rr++) {
            float mx = -1e30f;
#pragma unroll
            for (int nt = 0; nt < 8; nt++)
                mx = fmaxf(mx, fmaxf(sacc[nt][rr*2], sacc[nt][rr*2+1]));
            mx = fmaxf(mx, __shfl_xor_sync(0xffffffffu, mx, 1));
            mx = fmaxf(mx, __shfl_xor_sync(0xffffffffu, mx, 2));
            m_new[rr] = fmaxf(m_i[rr], mx);
            alpha[rr] = ex2(m_i[rr] - m_new[rr]);
            m_i[rr] = m_new[rr];
#pragma unroll
            for (int nd = 0; nd < 8; nd++) {
                Oacc[nd][rr*2]   *= alpha[rr];
                Oacc[nd][rr*2+1] *= alpha[rr];
            }
        }
        lacc[0] *= alpha[0]; lacc[1] *= alpha[0];
        lacc[2] *= alpha[1]; lacc[3] *= alpha[1];

        // ---- O += P V, l += P 1 (p via f16x2 ex2) ----
#pragma unroll
        for (int kc = 0; kc < 4; kc++) {
            uint32_t ph[4];
            ph[0] = ex2h2(packh(sacc[2*kc][0]   - m_new[0], sacc[2*kc][1]   - m_new[0]));
            ph[1] = ex2h2(packh(sacc[2*kc][2]   - m_new[1], sacc[2*kc][3]   - m_new[1]));
            ph[2] = ex2h2(packh(sacc[2*kc+1][0] - m_new[0], sacc[2*kc+1][1] - m_new[0]));
            ph[3] = ex2h2(packh(sacc[2*kc+1][2] - m_new[1], sacc[2*kc+1][3] - m_new[1]));
            mma_h(lacc, ph, HONES, HONES);
#pragma unroll
            for (int ndp = 0; ndp < 4; ndp++) {
                uint32_t bvh[4];
                ldm_x4t(bvh, st + voff[kc][ndp]);
#pragma unroll
                for (int nt2 = 0; nt2 < 2; nt2++) {
                    const int nd = ndp * 2 + nt2;
                    mma_h(Oacc[nd], ph, bvh[nt2*2], bvh[nt2*2+1]);
                }
            }
        }
    }

    // ---- epilogue: normalize, fp16 store ----
#pragma unroll
    for (int rr = 0; rr < 2; rr++) {
        const int row = wid * 16 + (lane >> 2) + rr * 8;
        const float inv = 1.f / lacc[rr * 2];
        const size_t rb = (size_t)(qrow0 + row) * 2048 + hoff + (lane & 3) * 2;
#pragma unroll
        for (int nd = 0; nd < 8; nd++) {
            float v0 = Oacc[nd][rr*2]   * inv;
            float v1 = Oacc[nd][rr*2+1] * inv;
            *(uint32_t*)(O + rb + nd * 8) = packh(v0, v1);
        }
    }
}

// ---------------------------------------------------------------------------
extern "C" void kernel_launch(void* const* d_in, const int* in_sizes, int n_in,
                              void* d_out, int out_size)
{
    const float* x  = (const float*)d_in[0];
    const float* Wq = (const float*)d_in[1];
    const float* bq = (const float*)d_in[2];
    const float* Wk = (const float*)d_in[3];
    const float* bk = (const float*)d_in[4];
    const float* Wv = (const float*)d_in[5];
    const float* bv = (const float*)d_in[6];
    const float* Wo = (const float*)d_in[7];
    const float* bo = (const float*)d_in[8];
    float* out = (float*)d_out;

    int8_t *x1, *x2, *a1, *a2;
    int8_t *wq1, *wq2, *wk1, *wk2, *wv1, *wv2, *wo1, *wo2;
    int8_t *q1, *q2, *k1, *k2;
    float *sx, *sa, *swq, *swk, *swv, *swo, *sq, *sk;
    __half *vh, *attn;
    cudaGetSymbolAddress((void**)&x1, g_x1);
    cudaGetSymbolAddress((void**)&x2, g_x2);
    cudaGetSymbolAddress((void**)&sx, g_sx);
    cudaGetSymbolAddress((void**)&a1, g_a1);
    cudaGetSymbolAddress((void**)&a2, g_a2);
    cudaGetSymbolAddress((void**)&sa, g_sa);
    cudaGetSymbolAddress((void**)&attn, g_attn);
    cudaGetSymbolAddress((void**)&wq1, g_wq1);
    cudaGetSymbolAddress((void**)&wq2, g_wq2);
    cudaGetSymbolAddress((void**)&swq, g_swq);
    cudaGetSymbolAddress((void**)&wk1, g_wk1);
    cudaGetSymbolAddress((void**)&wk2, g_wk2);
    cudaGetSymbolAddress((void**)&swk, g_swk);
    cudaGetSymbolAddress((void**)&wv1, g_wv1);
    cudaGetSymbolAddress((void**)&wv2, g_wv2);
    cudaGetSymbolAddress((void**)&swv, g_swv);
    cudaGetSymbolAddress((void**)&wo1, g_wo1);
    cudaGetSymbolAddress((void**)&wo2, g_wo2);
    cudaGetSymbolAddress((void**)&swo, g_swo);
    cudaGetSymbolAddress((void**)&q1, g_q1);
    cudaGetSymbolAddress((void**)&q2, g_q2);
    cudaGetSymbolAddress((void**)&k1, g_k1);
    cudaGetSymbolAddress((void**)&k2, g_k2);
    cudaGetSymbolAddress((void**)&sq, g_sq);
    cudaGetSymbolAddress((void**)&sk, g_sk);
    cudaGetSymbolAddress((void**)&vh, g_vh);

    cudaFuncSetAttribute(gemm_s8<0>,
                         cudaFuncAttributeMaxDynamicSharedMemorySize, GS8_SMEM);
    cudaFuncSetAttribute(gemm_s8<3>,
                         cudaFuncAttributeMaxDynamicSharedMemorySize, GS8_SMEM);
    cudaFuncSetAttribute(flash_hyb,
                         cudaFuncAttributeMaxDynamicSharedMemorySize, FA_SMEM);

    RQArgs rx{x,  x1,  x2,  sx,  M_};
    RQArgs rq{Wq, wq1, wq2, swq, E_};
    RQArgs rk{Wk, wk1, wk2, swk, E_};
    RQArgs rv{Wv, wv1, wv2, swv, E_};
    RQArgs ro{Wo, wo1, wo2, swo, E_};
    rowquant5<<<dim3(M_, 5), 256>>>(rx, rq, rk, rv, ro);

    GArgs aq{wq1, wq2, swq, bq, nullptr, nullptr, q1, q2, sq};
    GArgs ak{wk1, wk2, swk, bk, nullptr, nullptr, k1, k2, sk};
    GArgs av{wv1, wv2, swv, bv, nullptr, vh, nullptr, nullptr, nullptr};
    GArgs ao{wo1, wo2, swo, bo, out, nullptr, nullptr, nullptr, nullptr};

    dim3 gqkv(E_ / 128, M_ / 128, 3);
    gemm_s8<3><<<gqkv, 256, GS8_SMEM>>>(x1, x2, sx, aq, ak, av);

    dim3 ga(S_ / FQT, B_ * H_);     // (16, 64)
    flash_hyb<<<ga, 256, FA_SMEM>>>(q1, q2, sq, k1, k2, sk, vh, attn);

    rowquant_h<<<M_, 256>>>(attn, a1, a2, sa);

    dim3 go(E_ / 128, M_ / 128, 1);
    gemm_s8<0><<<go, 256, GS8_SMEM>>>(a1, a2, sa, ao, ao, ao);
}